// round 1
// baseline (speedup 1.0000x reference)
#include <cuda_runtime.h>

#define B_ 4
#define S_ 1024
#define E_ 1024
#define H_ 16
#define D_ 64
#define BH_ 64
#define NPOS_ 129
#define QD_LD 132
#define SCALING_ 0.125f

// Scratch (device globals; no runtime allocation allowed)
__device__ float g_q[B_*H_*S_*D_];      // [B,H,S,D]
__device__ float g_k[B_*H_*S_*D_];
__device__ float g_v[B_*H_*S_*D_];
__device__ float g_qd[BH_*S_*QD_LD];    // [BH,S,129(+pad)]
__device__ float g_attn[B_*S_*E_];      // [B,S,H*D]

// ---------------------------------------------------------------------------
// Kernel 1: QKV projection. C[m,n] = sum_k hs[m,k]*W[n,k] + b[n], scattered
// into g_q/g_k/g_v with [B,H,S,D] layout. M=4096, N=3072, K=1024. 128x128x8.
// ---------------------------------------------------------------------------
__global__ void qkv_gemm_kernel(const float* __restrict__ A,
                                const float* __restrict__ W,
                                const float* __restrict__ bias) {
    __shared__ float As[8][128];
    __shared__ float Bs[8][128];
    int tid = threadIdx.x;
    int bm = blockIdx.y * 128, bn = blockIdx.x * 128;
    int lrow = tid >> 1;
    int lk = (tid & 1) * 4;
    int ty = tid >> 4, tx = tid & 15;
    float acc[8][8];
#pragma unroll
    for (int i = 0; i < 8; i++)
#pragma unroll
        for (int j = 0; j < 8; j++) acc[i][j] = 0.f;

    for (int k0 = 0; k0 < 1024; k0 += 8) {
        float4 a4 = *(const float4*)(A + (size_t)(bm + lrow) * 1024 + k0 + lk);
        float4 b4 = *(const float4*)(W + (size_t)(bn + lrow) * 1024 + k0 + lk);
        __syncthreads();
        As[lk+0][lrow] = a4.x; As[lk+1][lrow] = a4.y; As[lk+2][lrow] = a4.z; As[lk+3][lrow] = a4.w;
        Bs[lk+0][lrow] = b4.x; Bs[lk+1][lrow] = b4.y; Bs[lk+2][lrow] = b4.z; Bs[lk+3][lrow] = b4.w;
        __syncthreads();
#pragma unroll
        for (int kk = 0; kk < 8; kk++) {
            float ar[8], br[8];
#pragma unroll
            for (int i = 0; i < 8; i++) ar[i] = As[kk][ty*8 + i];
#pragma unroll
            for (int j = 0; j < 8; j++) br[j] = Bs[kk][tx*8 + j];
#pragma unroll
            for (int i = 0; i < 8; i++)
#pragma unroll
                for (int j = 0; j < 8; j++) acc[i][j] += ar[i] * br[j];
        }
    }

#pragma unroll
    for (int i = 0; i < 8; i++) {
        int m = bm + ty*8 + i;
        int b = m >> 10, s = m & 1023;
#pragma unroll
        for (int j = 0; j < 8; j++) {
            int n = bn + tx*8 + j;
            float c = acc[i][j] + bias[n];
            int part = n >> 10;
            int h = (n & 1023) >> 6;
            int d = n & 63;
            float* dst = (part == 0) ? g_q : ((part == 1) ? g_k : g_v);
            dst[(((size_t)(b*H_ + h))*S_ + s)*D_ + d] = c;
        }
    }
}

// ---------------------------------------------------------------------------
// Kernel 2: qd[bh,l,p] = sum_d q[bh,l,d]*dist_emb[p,d]
// ---------------------------------------------------------------------------
__global__ void qd_kernel(const float* __restrict__ de) {
    __shared__ float sde[NPOS_][D_];   // 33 KB
    __shared__ float sq[32][D_];       // 8 KB
    int tid = threadIdx.x;
    int bh = blockIdx.y;
    int l0 = blockIdx.x * 32;
    for (int i = tid; i < NPOS_*D_; i += 256) ((float*)sde)[i] = de[i];
    const float* qsrc = g_q + ((size_t)bh*S_ + l0)*D_;
    for (int i = tid; i < 32*D_; i += 256) ((float*)sq)[i] = qsrc[i];
    __syncthreads();
    for (int o = tid; o < 32*NPOS_; o += 256) {
        int rr = o / NPOS_, p = o - rr*NPOS_;
        float s = 0.f;
#pragma unroll
        for (int d = 0; d < D_; d++) s += sq[rr][d] * sde[p][d];
        g_qd[((size_t)bh*S_ + l0 + rr)*QD_LD + p] = s;
    }
}

// ---------------------------------------------------------------------------
// Kernel 3: scores[bh,l,r] = (q·k + qd[bh,l,clip(r-l)+64]) * SCALING
// Per-bh NT GEMM 1024x1024x64, 128x128 tile, written into d_out weights.
// ---------------------------------------------------------------------------
__global__ void scores_kernel(float* __restrict__ wts) {
    __shared__ float As[8][128];
    __shared__ float Bs[8][128];
    int tid = threadIdx.x;
    int bh = blockIdx.z;
    const float* Q = g_q + (size_t)bh*S_*D_;
    const float* K = g_k + (size_t)bh*S_*D_;
    int bm = blockIdx.y * 128, bn = blockIdx.x * 128;
    int lrow = tid >> 1;
    int lk = (tid & 1) * 4;
    int ty = tid >> 4, tx = tid & 15;
    float acc[8][8];
#pragma unroll
    for (int i = 0; i < 8; i++)
#pragma unroll
        for (int j = 0; j < 8; j++) acc[i][j] = 0.f;

    for (int k0 = 0; k0 < 64; k0 += 8) {
        float4 a4 = *(const float4*)(Q + (size_t)(bm + lrow) * 64 + k0 + lk);
        float4 b4 = *(const float4*)(K + (size_t)(bn + lrow) * 64 + k0 + lk);
        __syncthreads();
        As[lk+0][lrow] = a4.x; As[lk+1][lrow] = a4.y; As[lk+2][lrow] = a4.z; As[lk+3][lrow] = a4.w;
        Bs[lk+0][lrow] = b4.x; Bs[lk+1][lrow] = b4.y; Bs[lk+2][lrow] = b4.z; Bs[lk+3][lrow] = b4.w;
        __syncthreads();
#pragma unroll
        for (int kk = 0; kk < 8; kk++) {
            float ar[8], br[8];
#pragma unroll
            for (int i = 0; i < 8; i++) ar[i] = As[kk][ty*8 + i];
#pragma unroll
            for (int j = 0; j < 8; j++) br[j] = Bs[kk][tx*8 + j];
#pragma unroll
            for (int i = 0; i < 8; i++)
#pragma unroll
                for (int j = 0; j < 8; j++) acc[i][j] += ar[i] * br[j];
        }
    }

    float* Wrow = wts + (size_t)bh*S_*S_;
#pragma unroll
    for (int i = 0; i < 8; i++) {
        int l = bm + ty*8 + i;
        const float* qd = g_qd + ((size_t)bh*S_ + l)*QD_LD;
#pragma unroll
        for (int j = 0; j < 8; j++) {
            int r = bn + tx*8 + j;
            int dl = r - l;
            dl = dl < -64 ? -64 : (dl > 64 ? 64 : dl);
            Wrow[(size_t)l*S_ + r] = (acc[i][j] + qd[dl + 64]) * SCALING_;
        }
    }
}

// ---------------------------------------------------------------------------
// Kernel 4: row softmax over last dim (1024), in place. One block per row.
// ---------------------------------------------------------------------------
__global__ void softmax_kernel(float* __restrict__ wts) {
    float* row = wts + (size_t)blockIdx.x * 1024;
    int tid = threadIdx.x;
    float4 v = ((float4*)row)[tid];
    float m = fmaxf(fmaxf(v.x, v.y), fmaxf(v.z, v.w));
#pragma unroll
    for (int o = 16; o > 0; o >>= 1) m = fmaxf(m, __shfl_xor_sync(0xffffffffu, m, o));
    __shared__ float sred[8];
    __shared__ float sred2[8];
    int wid = tid >> 5, lane = tid & 31;
    if (lane == 0) sred[wid] = m;
    __syncthreads();
    float mm = sred[0];
#pragma unroll
    for (int i = 1; i < 8; i++) mm = fmaxf(mm, sred[i]);
    v.x = __expf(v.x - mm); v.y = __expf(v.y - mm);
    v.z = __expf(v.z - mm); v.w = __expf(v.w - mm);
    float s = v.x + v.y + v.z + v.w;
#pragma unroll
    for (int o = 16; o > 0; o >>= 1) s += __shfl_xor_sync(0xffffffffu, s, o);
    if (lane == 0) sred2[wid] = s;
    __syncthreads();
    float tot = 0.f;
#pragma unroll
    for (int i = 0; i < 8; i++) tot += sred2[i];
    float inv = 1.0f / tot;
    v.x *= inv; v.y *= inv; v.z *= inv; v.w *= inv;
    ((float4*)row)[tid] = v;
}

// ---------------------------------------------------------------------------
// Kernel 5: PV. attn[bh,l,d] = sum_r w[bh,l,r]*v[bh,r,d]. NN GEMM per bh,
// 128(l) x 64(d) tile, K tile 16. Output into g_attn [B,S,H*D].
// ---------------------------------------------------------------------------
__global__ void pv_kernel(const float* __restrict__ wts) {
    __shared__ float Ws[16][130];
    __shared__ float Vs[16][68];
    int tid = threadIdx.x;
    int bh = blockIdx.y;
    int l0 = blockIdx.x * 128;
    const float* W = wts + (size_t)bh*S_*S_;
    const float* V = g_v + (size_t)bh*S_*D_;
    int ty = tid >> 4, tx = tid & 15;
    float acc[8][4];
#pragma unroll
    for (int i = 0; i < 8; i++)
#pragma unroll
        for (int j = 0; j < 4; j++) acc[i][j] = 0.f;

    for (int k0 = 0; k0 < 1024; k0 += 16) {
        __syncthreads();
#pragma unroll
        for (int q = 0; q < 2; q++) {
            int idx = tid*2 + q;            // 0..511
            int row = idx >> 2;             // 0..127
            int kq = (idx & 3) * 4;         // 0,4,8,12
            float4 a = *(const float4*)(W + (size_t)(l0 + row)*1024 + k0 + kq);
            Ws[kq+0][row] = a.x; Ws[kq+1][row] = a.y; Ws[kq+2][row] = a.z; Ws[kq+3][row] = a.w;
        }
        {
            int kk = tid >> 4;              // 0..15
            int c = (tid & 15) * 4;         // 0..60
            float4 b = *(const float4*)(V + (size_t)(k0 + kk)*64 + c);
            Vs[kk][c+0] = b.x; Vs[kk][c+1] = b.y; Vs[kk][c+2] = b.z; Vs[kk][c+3] = b.w;
        }
        __syncthreads();
#pragma unroll
        for (int kk = 0; kk < 16; kk++) {
            float a[8], b[4];
#pragma unroll
            for (int i = 0; i < 8; i++) a[i] = Ws[kk][ty*8 + i];
#pragma unroll
            for (int j = 0; j < 4; j++) b[j] = Vs[kk][tx*4 + j];
#pragma unroll
            for (int i = 0; i < 8; i++)
#pragma unroll
                for (int j = 0; j < 4; j++) acc[i][j] += a[i] * b[j];
        }
    }

    int b = bh >> 4, h = bh & 15;
#pragma unroll
    for (int i = 0; i < 8; i++) {
        int l = l0 + ty*8 + i;
#pragma unroll
        for (int j = 0; j < 4; j++) {
            int d = tx*4 + j;
            g_attn[(((size_t)b*S_ + l)*H_ + h)*D_ + d] = acc[i][j];
        }
    }
}

// ---------------------------------------------------------------------------
// Kernel 6: output projection. out[m,n] = sum_k attn[m,k]*out_w[n,k] + out_b[n]
// M=4096, N=1024, K=1024. 128x128x8 NT.
// ---------------------------------------------------------------------------
__global__ void outproj_kernel(const float* __restrict__ Wm,
                               const float* __restrict__ bias,
                               float* __restrict__ out) {
    __shared__ float As[8][128];
    __shared__ float Bs[8][128];
    int tid = threadIdx.x;
    int bm = blockIdx.y * 128, bn = blockIdx.x * 128;
    int lrow = tid >> 1;
    int lk = (tid & 1) * 4;
    int ty = tid >> 4, tx = tid & 15;
    float acc[8][8];
#pragma unroll
    for (int i = 0; i < 8; i++)
#pragma unroll
        for (int j = 0; j < 8; j++) acc[i][j] = 0.f;

    for (int k0 = 0; k0 < 1024; k0 += 8) {
        float4 a4 = *(const float4*)(g_attn + (size_t)(bm + lrow) * 1024 + k0 + lk);
        float4 b4 = *(const float4*)(Wm + (size_t)(bn + lrow) * 1024 + k0 + lk);
        __syncthreads();
        As[lk+0][lrow] = a4.x; As[lk+1][lrow] = a4.y; As[lk+2][lrow] = a4.z; As[lk+3][lrow] = a4.w;
        Bs[lk+0][lrow] = b4.x; Bs[lk+1][lrow] = b4.y; Bs[lk+2][lrow] = b4.z; Bs[lk+3][lrow] = b4.w;
        __syncthreads();
#pragma unroll
        for (int kk = 0; kk < 8; kk++) {
            float ar[8], br[8];
#pragma unroll
            for (int i = 0; i < 8; i++) ar[i] = As[kk][ty*8 + i];
#pragma unroll
            for (int j = 0; j < 8; j++) br[j] = Bs[kk][tx*8 + j];
#pragma unroll
            for (int i = 0; i < 8; i++)
#pragma unroll
                for (int j = 0; j < 8; j++) acc[i][j] += ar[i] * br[j];
        }
    }

#pragma unroll
    for (int i = 0; i < 8; i++) {
        int m = bm + ty*8 + i;
#pragma unroll
        for (int j = 0; j < 8; j++) {
            int n = bn + tx*8 + j;
            out[(size_t)m*1024 + n] = acc[i][j] + bias[n];
        }
    }
}

// ---------------------------------------------------------------------------
extern "C" void kernel_launch(void* const* d_in, const int* in_sizes, int n_in,
                              void* d_out, int out_size) {
    const float* hs       = (const float*)d_in[0];  // [4,1024,1024]
    const float* qkv_w    = (const float*)d_in[1];  // [3072,1024]
    const float* qkv_b    = (const float*)d_in[2];  // [3072]
    const float* out_w    = (const float*)d_in[3];  // [1024,1024]
    const float* out_b    = (const float*)d_in[4];  // [1024]
    const float* dist_emb = (const float*)d_in[5];  // [129,64]

    float* out = (float*)d_out;                      // attn_output [4,1024,1024]
    float* wts = out + (size_t)B_*S_*E_;             // attn_weights [4,16,1024,1024]

    qkv_gemm_kernel<<<dim3(24, 32), 256>>>(hs, qkv_w, qkv_b);
    qd_kernel<<<dim3(32, BH_), 256>>>(dist_emb);
    scores_kernel<<<dim3(8, 8, BH_), 256>>>(wts);
    softmax_kernel<<<BH_*S_, 256>>>(wts);
    pv_kernel<<<dim3(8, BH_), 256>>>(wts);
    outproj_kernel<<<dim3(8, 32), 256>>>(out_w, out_b, out);
}

// round 2
// speedup vs baseline: 1.2032x; 1.2032x over previous
#include <cuda_runtime.h>
#include <cstdint>

#define B_ 4
#define S_ 1024
#define E_ 1024
#define H_ 16
#define D_ 64
#define BH_ 64
#define NPOS_ 129
#define QD_LD 132
#define SCALING_ 0.125f

#define LDA_ 136
#define LDB_ 72

// Scratch (device globals; no runtime allocation allowed)
__device__ float g_q[B_*H_*S_*D_];      // [B,H,S,D]
__device__ float g_k[B_*H_*S_*D_];
__device__ float g_v[B_*H_*S_*D_];
__device__ float g_qd[BH_*S_*QD_LD];    // [BH,S,129(+pad)]
__device__ float g_attn[B_*S_*E_];      // [B,S,H*D]

// ---------------------------------------------------------------------------
// tf32 helpers
// ---------------------------------------------------------------------------
__device__ __forceinline__ uint32_t f2tf(float x) {
    uint32_t r; asm("cvt.rna.tf32.f32 %0, %1;" : "=r"(r) : "f"(x)); return r;
}
__device__ __forceinline__ void split_tf(float x, uint32_t& hi, uint32_t& lo) {
    hi = f2tf(x);
    lo = f2tf(x - __uint_as_float(hi));
}
__device__ __forceinline__ void mma8(float* c, const uint32_t* a, const uint32_t* b) {
    asm volatile(
        "mma.sync.aligned.m16n8k8.row.col.f32.tf32.tf32.f32 "
        "{%0,%1,%2,%3},{%4,%5,%6,%7},{%8,%9},{%0,%1,%2,%3};"
        : "+f"(c[0]), "+f"(c[1]), "+f"(c[2]), "+f"(c[3])
        : "r"(a[0]), "r"(a[1]), "r"(a[2]), "r"(a[3]), "r"(b[0]), "r"(b[1]));
}

// Shared-tile staging + warp-tile compute are identical across all 4 GEMMs:
// BM=128, BN=64, BK=16, 256 threads, 8 warps in a 4(M) x 2(N) grid,
// warp tile 32x32 -> 2 x 4 mma tiles of m16n8k8, tf32x2 (3 MMAs each).

struct Frag {
    float acc[2][4][4];
};

// compute over one staged BK=16 tile
__device__ __forceinline__ void tile_compute(
    const uint32_t (*AsH)[LDA_], const uint32_t (*AsL)[LDA_],
    const uint32_t (*BsH)[LDB_], const uint32_t (*BsL)[LDB_],
    int wm, int wn, int qr, int qc, Frag& f)
{
#pragma unroll
    for (int k8 = 0; k8 < 16; k8 += 8) {
        uint32_t aH[2][4], aL[2][4], bH[4][2], bL[4][2];
#pragma unroll
        for (int mt = 0; mt < 2; mt++) {
            int mb = wm*32 + mt*16 + qr;
            aH[mt][0] = AsH[k8+qc  ][mb];   aH[mt][1] = AsH[k8+qc  ][mb+8];
            aH[mt][2] = AsH[k8+qc+4][mb];   aH[mt][3] = AsH[k8+qc+4][mb+8];
            aL[mt][0] = AsL[k8+qc  ][mb];   aL[mt][1] = AsL[k8+qc  ][mb+8];
            aL[mt][2] = AsL[k8+qc+4][mb];   aL[mt][3] = AsL[k8+qc+4][mb+8];
        }
#pragma unroll
        for (int nt = 0; nt < 4; nt++) {
            int nb = wn*32 + nt*8 + qr;
            bH[nt][0] = BsH[k8+qc  ][nb];   bH[nt][1] = BsH[k8+qc+4][nb];
            bL[nt][0] = BsL[k8+qc  ][nb];   bL[nt][1] = BsL[k8+qc+4][nb];
        }
#pragma unroll
        for (int mt = 0; mt < 2; mt++)
#pragma unroll
            for (int nt = 0; nt < 4; nt++) {
                mma8(f.acc[mt][nt], aH[mt], bH[nt]);
                mma8(f.acc[mt][nt], aL[mt], bH[nt]);
                mma8(f.acc[mt][nt], aH[mt], bL[nt]);
            }
    }
}

// stage A tile (row-major [m][lda]) rows bm..bm+127, cols k0..k0+15
__device__ __forceinline__ void stage_A(
    const float* __restrict__ A, int lda, int bm, int k0, int tid,
    uint32_t (*AsH)[LDA_], uint32_t (*AsL)[LDA_])
{
    int ar = tid >> 1;
    int ac = (tid & 1) * 8;
    const float4* ap = (const float4*)(A + (size_t)(bm + ar) * lda + k0 + ac);
    float4 v0 = ap[0], v1 = ap[1];
    float fv[8] = {v0.x, v0.y, v0.z, v0.w, v1.x, v1.y, v1.z, v1.w};
#pragma unroll
    for (int j = 0; j < 8; j++) {
        uint32_t hi, lo; split_tf(fv[j], hi, lo);
        AsH[ac + j][ar] = hi;
        AsL[ac + j][ar] = lo;
    }
}

// stage B tile from NT weight layout: Bsrc row-major [n][ldb], rows bn..bn+63
__device__ __forceinline__ void stage_B_nt(
    const float* __restrict__ Bsrc, int ldb, int bn, int k0, int tid,
    uint32_t (*BsH)[LDB_], uint32_t (*BsL)[LDB_])
{
    int br = tid >> 2;
    int bc = (tid & 3) * 4;
    float4 v = *(const float4*)(Bsrc + (size_t)(bn + br) * ldb + k0 + bc);
    float fv[4] = {v.x, v.y, v.z, v.w};
#pragma unroll
    for (int j = 0; j < 4; j++) {
        uint32_t hi, lo; split_tf(fv[j], hi, lo);
        BsH[bc + j][br] = hi;
        BsL[bc + j][br] = lo;
    }
}

// stage B tile from NN layout: Bsrc row-major [k][64] (n contiguous)
__device__ __forceinline__ void stage_B_nn64(
    const float* __restrict__ Bsrc, int k0, int tid,
    uint32_t (*BsH)[LDB_], uint32_t (*BsL)[LDB_])
{
    int vr = tid >> 4;            // 0..15 (k)
    int vc = (tid & 15) * 4;      // 0..60 (n)
    float4 v = *(const float4*)(Bsrc + (size_t)(k0 + vr) * 64 + vc);
    float fv[4] = {v.x, v.y, v.z, v.w};
#pragma unroll
    for (int j = 0; j < 4; j++) {
        uint32_t hi, lo; split_tf(fv[j], hi, lo);
        BsH[vr][vc + j] = hi;
        BsL[vr][vc + j] = lo;
    }
}

// ---------------------------------------------------------------------------
// Kernel 1: QKV projection (NT, M=4096 N=3072 K=1024), scatter epilogue.
// ---------------------------------------------------------------------------
__global__ void qkv_gemm_kernel(const float* __restrict__ A,
                                const float* __restrict__ W,
                                const float* __restrict__ bias) {
    __shared__ uint32_t AsH[16][LDA_], AsL[16][LDA_];
    __shared__ uint32_t BsH[16][LDB_], BsL[16][LDB_];
    int tid = threadIdx.x;
    int bm = blockIdx.y * 128, bn = blockIdx.x * 64;
    int lane = tid & 31, wid = tid >> 5;
    int wm = wid >> 1, wn = wid & 1;
    int qr = lane >> 2, qc = lane & 3;
    Frag f;
#pragma unroll
    for (int i = 0; i < 2; i++)
#pragma unroll
        for (int j = 0; j < 4; j++)
#pragma unroll
            for (int e = 0; e < 4; e++) f.acc[i][j][e] = 0.f;

    for (int k0 = 0; k0 < 1024; k0 += 16) {
        __syncthreads();
        stage_A(A, 1024, bm, k0, tid, AsH, AsL);
        stage_B_nt(W, 1024, bn, k0, tid, BsH, BsL);
        __syncthreads();
        tile_compute(AsH, AsL, BsH, BsL, wm, wn, qr, qc, f);
    }

#pragma unroll
    for (int mt = 0; mt < 2; mt++)
#pragma unroll
        for (int nt = 0; nt < 4; nt++)
#pragma unroll
            for (int e = 0; e < 4; e++) {
                int m = bm + wm*32 + mt*16 + qr + (e >= 2 ? 8 : 0);
                int n = bn + wn*32 + nt*8 + 2*qc + (e & 1);
                float c = f.acc[mt][nt][e] + bias[n];
                int b = m >> 10, s = m & 1023;
                int part = n >> 10;
                int h = (n & 1023) >> 6;
                int d = n & 63;
                float* dst = (part == 0) ? g_q : ((part == 1) ? g_k : g_v);
                dst[(((size_t)(b*H_ + h))*S_ + s)*D_ + d] = c;
            }
}

// ---------------------------------------------------------------------------
// Kernel 2: qd[bh,l,p] = sum_d q[bh,l,d]*dist_emb[p,d]  (small, SIMT)
// ---------------------------------------------------------------------------
__global__ void qd_kernel(const float* __restrict__ de) {
    __shared__ float sde[NPOS_][D_];
    __shared__ float sq[32][D_];
    int tid = threadIdx.x;
    int bh = blockIdx.y;
    int l0 = blockIdx.x * 32;
    for (int i = tid; i < NPOS_*D_; i += 256) ((float*)sde)[i] = de[i];
    const float* qsrc = g_q + ((size_t)bh*S_ + l0)*D_;
    for (int i = tid; i < 32*D_; i += 256) ((float*)sq)[i] = qsrc[i];
    __syncthreads();
    for (int o = tid; o < 32*NPOS_; o += 256) {
        int rr = o / NPOS_, p = o - rr*NPOS_;
        float s = 0.f;
#pragma unroll
        for (int d = 0; d < D_; d++) s += sq[rr][d] * sde[p][d];
        g_qd[((size_t)bh*S_ + l0 + rr)*QD_LD + p] = s;
    }
}

// ---------------------------------------------------------------------------
// Kernel 3: scores (per-bh NT, M=N=1024, K=64) + qd bias epilogue
// ---------------------------------------------------------------------------
__global__ void scores_kernel(float* __restrict__ wts) {
    __shared__ uint32_t AsH[16][LDA_], AsL[16][LDA_];
    __shared__ uint32_t BsH[16][LDB_], BsL[16][LDB_];
    int tid = threadIdx.x;
    int bh = blockIdx.z;
    const float* Q = g_q + (size_t)bh*S_*D_;
    const float* K = g_k + (size_t)bh*S_*D_;
    int bm = blockIdx.y * 128, bn = blockIdx.x * 64;
    int lane = tid & 31, wid = tid >> 5;
    int wm = wid >> 1, wn = wid & 1;
    int qr = lane >> 2, qc = lane & 3;
    Frag f;
#pragma unroll
    for (int i = 0; i < 2; i++)
#pragma unroll
        for (int j = 0; j < 4; j++)
#pragma unroll
            for (int e = 0; e < 4; e++) f.acc[i][j][e] = 0.f;

    for (int k0 = 0; k0 < 64; k0 += 16) {
        __syncthreads();
        stage_A(Q, 64, bm, k0, tid, AsH, AsL);
        stage_B_nt(K, 64, bn, k0, tid, BsH, BsL);
        __syncthreads();
        tile_compute(AsH, AsL, BsH, BsL, wm, wn, qr, qc, f);
    }

    float* Wrow = wts + (size_t)bh*S_*S_;
#pragma unroll
    for (int mt = 0; mt < 2; mt++)
#pragma unroll
        for (int nt = 0; nt < 4; nt++)
#pragma unroll
            for (int e = 0; e < 4; e++) {
                int l = bm + wm*32 + mt*16 + qr + (e >= 2 ? 8 : 0);
                int r = bn + wn*32 + nt*8 + 2*qc + (e & 1);
                int dl = r - l;
                dl = dl < -64 ? -64 : (dl > 64 ? 64 : dl);
                float qdv = g_qd[((size_t)bh*S_ + l)*QD_LD + dl + 64];
                Wrow[(size_t)l*S_ + r] = (f.acc[mt][nt][e] + qdv) * SCALING_;
            }
}

// ---------------------------------------------------------------------------
// Kernel 4: row softmax (unchanged; near HBM roofline)
// ---------------------------------------------------------------------------
__global__ void softmax_kernel(float* __restrict__ wts) {
    float* row = wts + (size_t)blockIdx.x * 1024;
    int tid = threadIdx.x;
    float4 v = ((float4*)row)[tid];
    float m = fmaxf(fmaxf(v.x, v.y), fmaxf(v.z, v.w));
#pragma unroll
    for (int o = 16; o > 0; o >>= 1) m = fmaxf(m, __shfl_xor_sync(0xffffffffu, m, o));
    __shared__ float sred[8];
    __shared__ float sred2[8];
    int wid = tid >> 5, lane = tid & 31;
    if (lane == 0) sred[wid] = m;
    __syncthreads();
    float mm = sred[0];
#pragma unroll
    for (int i = 1; i < 8; i++) mm = fmaxf(mm, sred[i]);
    v.x = __expf(v.x - mm); v.y = __expf(v.y - mm);
    v.z = __expf(v.z - mm); v.w = __expf(v.w - mm);
    float s = v.x + v.y + v.z + v.w;
#pragma unroll
    for (int o = 16; o > 0; o >>= 1) s += __shfl_xor_sync(0xffffffffu, s, o);
    if (lane == 0) sred2[wid] = s;
    __syncthreads();
    float tot = 0.f;
#pragma unroll
    for (int i = 0; i < 8; i++) tot += sred2[i];
    float inv = 1.0f / tot;
    v.x *= inv; v.y *= inv; v.z *= inv; v.w *= inv;
    ((float4*)row)[tid] = v;
}

// ---------------------------------------------------------------------------
// Kernel 5: PV (per-bh NN, M=1024 N=64 K=1024) -> g_attn [B,S,H*D]
// ---------------------------------------------------------------------------
__global__ void pv_kernel(const float* __restrict__ wts) {
    __shared__ uint32_t AsH[16][LDA_], AsL[16][LDA_];
    __shared__ uint32_t BsH[16][LDB_], BsL[16][LDB_];
    int tid = threadIdx.x;
    int bh = blockIdx.y;
    int bm = blockIdx.x * 128;
    const float* W = wts + (size_t)bh*S_*S_;
    const float* V = g_v + (size_t)bh*S_*D_;
    int lane = tid & 31, wid = tid >> 5;
    int wm = wid >> 1, wn = wid & 1;
    int qr = lane >> 2, qc = lane & 3;
    Frag f;
#pragma unroll
    for (int i = 0; i < 2; i++)
#pragma unroll
        for (int j = 0; j < 4; j++)
#pragma unroll
            for (int e = 0; e < 4; e++) f.acc[i][j][e] = 0.f;

    for (int k0 = 0; k0 < 1024; k0 += 16) {
        __syncthreads();
        stage_A(W, 1024, bm, k0, tid, AsH, AsL);
        stage_B_nn64(V, k0, tid, BsH, BsL);
        __syncthreads();
        tile_compute(AsH, AsL, BsH, BsL, wm, wn, qr, qc, f);
    }

    int b = bh >> 4, h = bh & 15;
#pragma unroll
    for (int mt = 0; mt < 2; mt++)
#pragma unroll
        for (int nt = 0; nt < 4; nt++)
#pragma unroll
            for (int e = 0; e < 4; e++) {
                int l = bm + wm*32 + mt*16 + qr + (e >= 2 ? 8 : 0);
                int d = wn*32 + nt*8 + 2*qc + (e & 1);
                g_attn[(((size_t)b*S_ + l)*H_ + h)*D_ + d] = f.acc[mt][nt][e];
            }
}

// ---------------------------------------------------------------------------
// Kernel 6: output projection (NT, M=4096 N=1024 K=1024)
// ---------------------------------------------------------------------------
__global__ void outproj_kernel(const float* __restrict__ Wm,
                               const float* __restrict__ bias,
                               float* __restrict__ out) {
    __shared__ uint32_t AsH[16][LDA_], AsL[16][LDA_];
    __shared__ uint32_t BsH[16][LDB_], BsL[16][LDB_];
    int tid = threadIdx.x;
    int bm = blockIdx.y * 128, bn = blockIdx.x * 64;
    int lane = tid & 31, wid = tid >> 5;
    int wm = wid >> 1, wn = wid & 1;
    int qr = lane >> 2, qc = lane & 3;
    Frag f;
#pragma unroll
    for (int i = 0; i < 2; i++)
#pragma unroll
        for (int j = 0; j < 4; j++)
#pragma unroll
            for (int e = 0; e < 4; e++) f.acc[i][j][e] = 0.f;

    for (int k0 = 0; k0 < 1024; k0 += 16) {
        __syncthreads();
        stage_A(g_attn, 1024, bm, k0, tid, AsH, AsL);
        stage_B_nt(Wm, 1024, bn, k0, tid, BsH, BsL);
        __syncthreads();
        tile_compute(AsH, AsL, BsH, BsL, wm, wn, qr, qc, f);
    }

#pragma unroll
    for (int mt = 0; mt < 2; mt++)
#pragma unroll
        for (int nt = 0; nt < 4; nt++)
#pragma unroll
            for (int e = 0; e < 4; e++) {
                int m = bm + wm*32 + mt*16 + qr + (e >= 2 ? 8 : 0);
                int n = bn + wn*32 + nt*8 + 2*qc + (e & 1);
                out[(size_t)m*1024 + n] = f.acc[mt][nt][e] + bias[n];
            }
}

// ---------------------------------------------------------------------------
extern "C" void kernel_launch(void* const* d_in, const int* in_sizes, int n_in,
                              void* d_out, int out_size) {
    const float* hs       = (const float*)d_in[0];  // [4,1024,1024]
    const float* qkv_w    = (const float*)d_in[1];  // [3072,1024]
    const float* qkv_b    = (const float*)d_in[2];  // [3072]
    const float* out_w    = (const float*)d_in[3];  // [1024,1024]
    const float* out_b    = (const float*)d_in[4];  // [1024]
    const float* dist_emb = (const float*)d_in[5];  // [129,64]

    float* out = (float*)d_out;                      // attn_output [4,1024,1024]
    float* wts = out + (size_t)B_*S_*E_;             // attn_weights [4,16,1024,1024]

    qkv_gemm_kernel<<<dim3(48, 32), 256>>>(hs, qkv_w, qkv_b);
    qd_kernel<<<dim3(32, BH_), 256>>>(dist_emb);
    scores_kernel<<<dim3(16, 8, BH_), 256>>>(wts);
    softmax_kernel<<<BH_*S_, 256>>>(wts);
    pv_kernel<<<dim3(8, BH_), 256>>>(wts);
    outproj_kernel<<<dim3(16, 32), 256>>>(out_w, out_b, out);
}